// round 1
// baseline (speedup 1.0000x reference)
#include <cuda_runtime.h>

// Fused 2-layer LSTM + FC head, fp32, packed f32x2 FMA (FFMA2) on sm_103a.
// Grid: 128 CTAs x 256 threads, 16 batch rows per CTA, all weights + h/c in SMEM/regs.
// R1: baseline fused design. Predicted ~1.2-1.6 ms, FMA-pipe bound.

typedef unsigned long long u64;

#define TT      512
#define NBATCH  16
#define NTH     256
#define NCTA    128

// shared memory layout (float offsets)
#define OFF_W1S   0        // [64 k][64 j][4 g]            16384
#define OFF_W1XS  16384    // [4 i][64 j][4 g]             1024
#define OFF_B1S   17408    // [64 j][4 g]                  256
#define OFF_W2S   17664    // [96 k][32 j][4 g]            12288
#define OFF_B2S   29952    // [32 j][4 g]                  128
#define OFF_H1    30080    // [2][16 b][130] (dup pairs)   4160
#define OFF_H2    34240    // [2][16 b][66]  (dup pairs)   2112
#define OFF_XBUF  36352    // [16 b][4]                    64
#define OFF_FC1W  36416    // [16][32]                     512
#define OFF_FC1B  36928    // 16
#define OFF_FC2W  36944    // 16
#define OFF_FC2B  36960    // 1
#define SMEM_FLOATS 36961
#define SMEM_BYTES  (SMEM_FLOATS * 4)

#define H1PITCH 130   // floats per batch row (64 dup values + pad); 65 u64
#define H2PITCH 66    // 32 dup values + pad; 33 u64

// packed dual-fp32 FMA: d = a*b + d elementwise on (lo,hi)
__device__ __forceinline__ void FMA2(u64 &d, u64 a, u64 b) {
    asm("fma.rn.f32x2 %0, %1, %2, %0;" : "+l"(d) : "l"(a), "l"(b));
}

__device__ __forceinline__ float sigf(float x) {
    return __fdividef(1.0f, 1.0f + __expf(-x));
}
__device__ __forceinline__ float tanhf_(float x) {
    float e = __expf(2.0f * x);
    return 1.0f - __fdividef(2.0f, e + 1.0f);
}

__global__ __launch_bounds__(NTH, 1)
void lstm_fused(const float* __restrict__ x,
                const float* __restrict__ Wih1, const float* __restrict__ Whh1,
                const float* __restrict__ bih1, const float* __restrict__ bhh1,
                const float* __restrict__ Wih2, const float* __restrict__ Whh2,
                const float* __restrict__ bih2, const float* __restrict__ bhh2,
                const float* __restrict__ fc1w, const float* __restrict__ fc1b,
                const float* __restrict__ fc2w, const float* __restrict__ fc2b,
                float* __restrict__ out)
{
    extern __shared__ float s[];
    const int tid = threadIdx.x;
    const int b0  = blockIdx.x * NBATCH;

    // ---- stage weights into SMEM, gate-interleaved [k][j][i,f,g,o] ----
    for (int idx = tid; idx < 16384; idx += NTH) {
        int g = idx & 3, j = (idx >> 2) & 63, k = idx >> 8;
        s[OFF_W1S + idx] = Whh1[(g * 64 + j) * 64 + k];
    }
    for (int idx = tid; idx < 1024; idx += NTH) {
        int g = idx & 3, j = (idx >> 2) & 63, i = idx >> 8;
        s[OFF_W1XS + idx] = Wih1[(g * 64 + j) * 4 + i];
    }
    for (int idx = tid; idx < 256; idx += NTH) {
        int g = idx & 3, j = idx >> 2;
        s[OFF_B1S + idx] = bih1[g * 64 + j] + bhh1[g * 64 + j];
    }
    for (int idx = tid; idx < 12288; idx += NTH) {
        int g = idx & 3, j = (idx >> 2) & 31, k = idx >> 7;
        s[OFF_W2S + idx] = (k < 64) ? Wih2[(g * 32 + j) * 64 + k]
                                    : Whh2[(g * 32 + j) * 32 + (k - 64)];
    }
    for (int idx = tid; idx < 128; idx += NTH) {
        int g = idx & 3, j = idx >> 2;
        s[OFF_B2S + idx] = bih2[g * 32 + j] + bhh2[g * 32 + j];
    }
    for (int idx = tid; idx < 512; idx += NTH) s[OFF_FC1W + idx] = fc1w[idx];
    if (tid < 16) s[OFF_FC1B + tid] = fc1b[tid];
    if (tid < 16) s[OFF_FC2W + tid] = fc2w[tid];
    if (tid == 0) s[OFF_FC2B] = fc2b[0];
    for (int idx = tid; idx < 2 * 16 * H1PITCH; idx += NTH) s[OFF_H1 + idx] = 0.f;
    for (int idx = tid; idx < 2 * 16 * H2PITCH; idx += NTH) s[OFF_H2 + idx] = 0.f;

    // thread roles
    const int j1  = tid >> 2;   // 0..63  hidden unit (layer 1)
    const int bq1 = tid & 3;    // handles batches bq1*4 .. bq1*4+3
    const int j2  = tid >> 3;   // 0..31  hidden unit (layer 2)
    const int bq2 = tid & 7;    // handles batches bq2*2, bq2*2+1

    float c1[4] = {0.f, 0.f, 0.f, 0.f};
    float c2[2] = {0.f, 0.f};

    float4 xreg = make_float4(0.f, 0.f, 0.f, 0.f);
    if (tid < NBATCH)
        xreg = *(const float4*)&x[(b0 + tid) * (TT * 4)];

    int cur = 0;
    for (int t = 0; t < TT; ++t) {
        const int nxt = cur ^ 1;

        // stage x_t (prefetched last step), prefetch x_{t+1}
        if (tid < NBATCH) {
            *(float4*)&s[OFF_XBUF + tid * 4] = xreg;
            if (t + 1 < TT)
                xreg = *(const float4*)&x[((b0 + tid) * TT + t + 1) * 4];
        }
        __syncthreads();

        // ---------------- Layer 1 ----------------
        {
            const u64* Wp = (const u64*)&s[OFF_W1S];
            const u64* hc = (const u64*)&s[OFF_H1 + cur * (16 * H1PITCH)];
            u64 a01[4], a23[4];
            #pragma unroll
            for (int q = 0; q < 4; ++q) { a01[q] = 0ULL; a23[q] = 0ULL; }

            #pragma unroll 4
            for (int k4 = 0; k4 < 16; ++k4) {
                u64 w[8];
                #pragma unroll
                for (int kk = 0; kk < 4; ++kk) {
                    ulonglong2 ww = *(const ulonglong2*)&Wp[((k4 * 4 + kk) * 64 + j1) * 2];
                    w[kk * 2] = ww.x; w[kk * 2 + 1] = ww.y;
                }
                #pragma unroll
                for (int bi = 0; bi < 4; ++bi) {
                    const u64* hb = hc + (bq1 * 4 + bi) * (H1PITCH / 2) + k4 * 4;
                    u64 h0 = hb[0], h1v = hb[1], h2v = hb[2], h3v = hb[3];
                    FMA2(a01[bi], w[0], h0);  FMA2(a23[bi], w[1], h0);
                    FMA2(a01[bi], w[2], h1v); FMA2(a23[bi], w[3], h1v);
                    FMA2(a01[bi], w[4], h2v); FMA2(a23[bi], w[5], h2v);
                    FMA2(a01[bi], w[6], h3v); FMA2(a23[bi], w[7], h3v);
                }
            }

            const float4 wx0 = *(const float4*)&s[OFF_W1XS + (0 * 64 + j1) * 4];
            const float4 wx1 = *(const float4*)&s[OFF_W1XS + (1 * 64 + j1) * 4];
            const float4 wx2 = *(const float4*)&s[OFF_W1XS + (2 * 64 + j1) * 4];
            const float4 wx3 = *(const float4*)&s[OFF_W1XS + (3 * 64 + j1) * 4];
            const float4 bb  = *(const float4*)&s[OFF_B1S + j1 * 4];

            #pragma unroll
            for (int bi = 0; bi < 4; ++bi) {
                int b = bq1 * 4 + bi;
                union { u64 u; float2 f; } A, Bc;
                A.u = a01[bi]; Bc.u = a23[bi];
                float gi = A.f.x, gf = A.f.y, gg = Bc.f.x, go = Bc.f.y;
                float4 xv = *(const float4*)&s[OFF_XBUF + b * 4];
                gi = fmaf(wx0.x, xv.x, gi); gf = fmaf(wx0.y, xv.x, gf);
                gg = fmaf(wx0.z, xv.x, gg); go = fmaf(wx0.w, xv.x, go);
                gi = fmaf(wx1.x, xv.y, gi); gf = fmaf(wx1.y, xv.y, gf);
                gg = fmaf(wx1.z, xv.y, gg); go = fmaf(wx1.w, xv.y, go);
                gi = fmaf(wx2.x, xv.z, gi); gf = fmaf(wx2.y, xv.z, gf);
                gg = fmaf(wx2.z, xv.z, gg); go = fmaf(wx2.w, xv.z, go);
                gi = fmaf(wx3.x, xv.w, gi); gf = fmaf(wx3.y, xv.w, gf);
                gg = fmaf(wx3.z, xv.w, gg); go = fmaf(wx3.w, xv.w, go);

                gi = sigf(gi + bb.x);
                gf = sigf(gf + bb.y);
                gg = tanhf_(gg + bb.z);
                go = sigf(go + bb.w);
                float c = fmaf(gf, c1[bi], gi * gg);
                c1[bi] = c;
                float h = go * tanhf_(c);
                *(float2*)&s[OFF_H1 + nxt * (16 * H1PITCH) + b * H1PITCH + 2 * j1] =
                    make_float2(h, h);
            }
        }
        __syncthreads();

        // ---------------- Layer 2 ----------------
        {
            const u64* Wp  = (const u64*)&s[OFF_W2S];
            const u64* h1n = (const u64*)&s[OFF_H1 + nxt * (16 * H1PITCH)];
            const u64* h2c = (const u64*)&s[OFF_H2 + cur * (16 * H2PITCH)];
            u64 a01[2] = {0ULL, 0ULL}, a23[2] = {0ULL, 0ULL};

            // input part: k over h1 (64)
            #pragma unroll 4
            for (int k4 = 0; k4 < 16; ++k4) {
                u64 w[8];
                #pragma unroll
                for (int kk = 0; kk < 4; ++kk) {
                    ulonglong2 ww = *(const ulonglong2*)&Wp[((k4 * 4 + kk) * 32 + j2) * 2];
                    w[kk * 2] = ww.x; w[kk * 2 + 1] = ww.y;
                }
                #pragma unroll
                for (int bi = 0; bi < 2; ++bi) {
                    const u64* hb = h1n + (bq2 * 2 + bi) * (H1PITCH / 2) + k4 * 4;
                    u64 h0 = hb[0], h1v = hb[1], h2v = hb[2], h3v = hb[3];
                    FMA2(a01[bi], w[0], h0);  FMA2(a23[bi], w[1], h0);
                    FMA2(a01[bi], w[2], h1v); FMA2(a23[bi], w[3], h1v);
                    FMA2(a01[bi], w[4], h2v); FMA2(a23[bi], w[5], h2v);
                    FMA2(a01[bi], w[6], h3v); FMA2(a23[bi], w[7], h3v);
                }
            }
            // recurrent part: k over h2 (32), weight rows 64..95
            #pragma unroll 4
            for (int k4 = 0; k4 < 8; ++k4) {
                u64 w[8];
                #pragma unroll
                for (int kk = 0; kk < 4; ++kk) {
                    ulonglong2 ww = *(const ulonglong2*)&Wp[((64 + k4 * 4 + kk) * 32 + j2) * 2];
                    w[kk * 2] = ww.x; w[kk * 2 + 1] = ww.y;
                }
                #pragma unroll
                for (int bi = 0; bi < 2; ++bi) {
                    const u64* hb = h2c + (bq2 * 2 + bi) * (H2PITCH / 2) + k4 * 4;
                    u64 h0 = hb[0], h1v = hb[1], h2v = hb[2], h3v = hb[3];
                    FMA2(a01[bi], w[0], h0);  FMA2(a23[bi], w[1], h0);
                    FMA2(a01[bi], w[2], h1v); FMA2(a23[bi], w[3], h1v);
                    FMA2(a01[bi], w[4], h2v); FMA2(a23[bi], w[5], h2v);
                    FMA2(a01[bi], w[6], h3v); FMA2(a23[bi], w[7], h3v);
                }
            }

            const float4 bb = *(const float4*)&s[OFF_B2S + j2 * 4];
            #pragma unroll
            for (int bi = 0; bi < 2; ++bi) {
                int b = bq2 * 2 + bi;
                union { u64 u; float2 f; } A, Bc;
                A.u = a01[bi]; Bc.u = a23[bi];
                float gi = sigf(A.f.x + bb.x);
                float gf = sigf(A.f.y + bb.y);
                float gg = tanhf_(Bc.f.x + bb.z);
                float go = sigf(Bc.f.y + bb.w);
                float c = fmaf(gf, c2[bi], gi * gg);
                c2[bi] = c;
                float h = go * tanhf_(c);
                *(float2*)&s[OFF_H2 + nxt * (16 * H2PITCH) + b * H2PITCH + 2 * j2] =
                    make_float2(h, h);
            }
        }
        cur ^= 1;
    }

    __syncthreads();

    // ---- FC head on last h2 ----
    if (tid < NBATCH) {
        const float* hb = &s[OFF_H2 + cur * (16 * H2PITCH) + tid * H2PITCH];
        float o = s[OFF_FC2B];
        #pragma unroll
        for (int f = 0; f < 16; ++f) {
            float a = s[OFF_FC1B + f];
            #pragma unroll
            for (int k = 0; k < 32; ++k)
                a = fmaf(s[OFF_FC1W + f * 32 + k], hb[2 * k], a);
            a = fmaxf(a, 0.f);
            o = fmaf(s[OFF_FC2W + f], a, o);
        }
        out[b0 + tid] = o;
    }
}

extern "C" void kernel_launch(void* const* d_in, const int* in_sizes, int n_in,
                              void* d_out, int out_size) {
    const float* x    = (const float*)d_in[0];
    const float* Wih1 = (const float*)d_in[1];
    const float* Whh1 = (const float*)d_in[2];
    const float* bih1 = (const float*)d_in[3];
    const float* bhh1 = (const float*)d_in[4];
    const float* Wih2 = (const float*)d_in[5];
    const float* Whh2 = (const float*)d_in[6];
    const float* bih2 = (const float*)d_in[7];
    const float* bhh2 = (const float*)d_in[8];
    const float* fc1w = (const float*)d_in[9];
    const float* fc1b = (const float*)d_in[10];
    const float* fc2w = (const float*)d_in[11];
    const float* fc2b = (const float*)d_in[12];
    float* out = (float*)d_out;

    cudaFuncSetAttribute(lstm_fused, cudaFuncAttributeMaxDynamicSharedMemorySize,
                         SMEM_BYTES);
    lstm_fused<<<NCTA, NTH, SMEM_BYTES>>>(x, Wih1, Whh1, bih1, bhh1,
                                          Wih2, Whh2, bih2, bhh2,
                                          fc1w, fc1b, fc2w, fc2b, out);
}